// round 4
// baseline (speedup 1.0000x reference)
#include <cuda_runtime.h>
#include <cuda_bf16.h>
#include <cstdint>

#define PV   113
#define PVP  128
#define DIM  128
#define NH   4
#define DHD  32
#define HID  512
#define NCOMBO 226
#define NPAIR (PV*PV)      // 12769
#define NTOK  (NPAIR*2)    // 25538
#define PPB   64           // pairs per GEMM CTA (128 rows)
#define KCH   64
#define NCHUNK (HID/KCH)   // 8
#define GEMM_GRID ((NPAIR + PPB - 1)/PPB)   // 200

// ---------------- device scratch (zero-initialized) ----------------
__device__ float g_OW1[NH*DHD*HID];
__device__ float g_OU [NH*DHD*PV];
__device__ float g_b2u[PV];
__device__ float g_qk [2*NCOMBO*DIM];
__device__ float g_EW1[(NCOMBO+2)*HID];           // padded rows (zeros)
__device__ float g_EU [(NCOMBO+2)*PVP];           // stride 128, padded
__device__ float g_AW1[(NCOMBO+2)*NH*HID];        // padded
__device__ float g_AU [(NCOMBO+2)*NH*PVP];        // stride 128, padded
__device__ float g_pat[(NPAIR+PPB)*16];           // padded (zeros)
__device__ __nv_bfloat16 g_Bh[HID*DIM];           // [j][n] W2U hi
__device__ __nv_bfloat16 g_Bl[HID*DIM];           // [j][n] W2U lo
__device__ float g_table[(size_t)NTOK*PV];

// ---------------- helpers ----------------
__device__ __forceinline__ uint32_t smem_u32(const void* p){
    uint32_t a;
    asm("{ .reg .u64 t; cvta.to.shared.u64 t, %1; cvt.u32.u64 %0, t; }" : "=r"(a) : "l"(p));
    return a;
}
__device__ __forceinline__ void ldsm4(uint32_t* r, uint32_t a){
    asm volatile("ldmatrix.sync.aligned.m8n8.x4.shared.b16 {%0,%1,%2,%3}, [%4];"
        : "=r"(r[0]),"=r"(r[1]),"=r"(r[2]),"=r"(r[3]) : "r"(a));
}
__device__ __forceinline__ void ldsm4t(uint32_t* r, uint32_t a){
    asm volatile("ldmatrix.sync.aligned.m8n8.x4.trans.shared.b16 {%0,%1,%2,%3}, [%4];"
        : "=r"(r[0]),"=r"(r[1]),"=r"(r[2]),"=r"(r[3]) : "r"(a));
}
__device__ __forceinline__ void mma16816(float* c, const uint32_t* a, uint32_t b0, uint32_t b1){
    asm volatile("mma.sync.aligned.m16n8k16.row.col.f32.bf16.bf16.f32 "
        "{%0,%1,%2,%3}, {%4,%5,%6,%7}, {%8,%9}, {%0,%1,%2,%3};"
        : "+f"(c[0]),"+f"(c[1]),"+f"(c[2]),"+f"(c[3])
        : "r"(a[0]),"r"(a[1]),"r"(a[2]),"r"(a[3]), "r"(b0),"r"(b1));
}
__device__ __forceinline__ int permA(int m){ int t = m & 7; return (t>>1) | ((t&1)<<2); }

// ---------------- A1: fold weights (+ bf16-split B) ----------------
__global__ void kA1(const float* __restrict__ WO, const float* __restrict__ W1,
                    const float* __restrict__ W2, const float* __restrict__ b2,
                    const float* __restrict__ WU){
    int t = blockIdx.x*256 + threadIdx.x;
    if (t < 65536) {
        int j = t & 511, hi = t >> 9;
        const float* wo = WO + hi*DIM;
        float s = 0.f;
        #pragma unroll 8
        for (int d=0; d<DIM; d++) s += wo[d]*W1[d*HID + j];
        g_OW1[t] = s;
    } else if (t < 80000) {
        int u = t - 65536; int p = u % PV; int hi = u / PV;
        const float* wo = WO + hi*DIM; const float* wu = WU + p*DIM;
        float s = 0.f;
        #pragma unroll 8
        for (int d=0; d<DIM; d++) s += wo[d]*wu[d];
        g_OU[u] = s;
    } else if (t < 145536) {
        int u = t - 80000; int n = u & 127; int j = u >> 7;
        float s = 0.f;
        if (n < PV) {
            const float* w2 = W2 + j*DIM; const float* wu = WU + n*DIM;
            #pragma unroll 8
            for (int d=0; d<DIM; d++) s += w2[d]*wu[d];
        }
        __nv_bfloat16 bh = __float2bfloat16(s);
        g_Bh[u] = bh;
        g_Bl[u] = __float2bfloat16(s - __bfloat162float(bh));
    } else if (t < 145649) {
        int p = t - 145536;
        const float* wu = WU + p*DIM;
        float s = 0.f;
        #pragma unroll 8
        for (int d=0; d<DIM; d++) s += b2[d]*wu[d];
        g_b2u[p] = s;
    }
}

// ---------------- A2: per-combo tables ----------------
__global__ void kA2(const float* __restrict__ tok_emb, const float* __restrict__ pos_emb,
                    const float* __restrict__ WQ, const float* __restrict__ WK,
                    const float* __restrict__ WV, const float* __restrict__ W1,
                    const float* __restrict__ b1, const float* __restrict__ WU){
    __shared__ float e[DIM];
    __shared__ float vv[DIM];
    const int c = blockIdx.x;
    const int tk = c >> 1, pos = c & 1;
    const int tid = threadIdx.x;
    if (tid < DIM) e[tid] = tok_emb[tk*DIM + tid] + pos_emb[pos*DIM + tid];
    __syncthreads();

    for (int o = tid; o < 384; o += 256) {
        int sel = o >> 7; int idx = o & 127;
        const float* W = (sel==0) ? WQ : ((sel==1) ? WK : WV);
        int h = idx >> 5, i = idx & 31;
        float s = 0.f;
        #pragma unroll 8
        for (int d=0; d<DIM; d++) s += e[d]*W[(h*DIM + d)*DHD + i];
        if (sel < 2) g_qk[(sel*NCOMBO + c)*DIM + idx] = s;
        else         vv[idx] = s;
    }
    __syncthreads();

    for (int j = tid; j < HID; j += 256) {
        float s = b1[j];
        #pragma unroll 8
        for (int d=0; d<DIM; d++) s += e[d]*W1[d*HID + j];
        g_EW1[c*HID + j] = s;
    }
    if (tid < PV) {
        const float* wu = WU + tid*DIM;
        float s = g_b2u[tid];
        #pragma unroll 8
        for (int d=0; d<DIM; d++) s += e[d]*wu[d];
        g_EU[c*PVP + tid] = s;
    }
    for (int o = tid; o < NH*HID; o += 256) {
        int h = o >> 9; int j = o & 511;
        float s = 0.f;
        #pragma unroll
        for (int i=0; i<DHD; i++) s += vv[h*DHD + i]*g_OW1[(h*DHD + i)*HID + j];
        g_AW1[(c*NH + h)*HID + j] = s;
    }
    for (int o = tid; o < NH*PV; o += 256) {
        int h = o / PV; int p = o % PV;
        float s = 0.f;
        #pragma unroll
        for (int i=0; i<DHD; i++) s += vv[h*DHD + i]*g_OU[(h*DHD + i)*PV + p];
        g_AU[(c*NH + h)*PVP + p] = s;
    }
}

// ---------------- kPat: one thread per pair ----------------
__global__ void kPat(){
    int pair = blockIdx.x*256 + threadIdx.x;
    if (pair >= NPAIR) return;
    int a = pair / PV, b = pair % PV;
    int ca = 2*a, cb = 2*b + 1;
    float pat[16];
    #pragma unroll
    for (int h=0; h<NH; h++){
        const float* qa = g_qk + (0*NCOMBO + ca)*DIM + h*DHD;
        const float* qb = g_qk + (0*NCOMBO + cb)*DIM + h*DHD;
        const float* ka = g_qk + (1*NCOMBO + ca)*DIM + h*DHD;
        const float* kb = g_qk + (1*NCOMBO + cb)*DIM + h*DHD;
        float s00=0.f, s01=0.f, s10=0.f, s11=0.f;
        #pragma unroll
        for (int i=0;i<DHD;i+=4){
            float4 va = *(const float4*)(qa+i);
            float4 vb = *(const float4*)(qb+i);
            float4 wa = *(const float4*)(ka+i);
            float4 wb = *(const float4*)(kb+i);
            s00 += va.x*wa.x + va.y*wa.y + va.z*wa.z + va.w*wa.w;
            s01 += va.x*wb.x + va.y*wb.y + va.z*wb.z + va.w*wb.w;
            s10 += vb.x*wa.x + vb.y*wa.y + vb.z*wa.z + vb.w*wa.w;
            s11 += vb.x*wb.x + vb.y*wb.y + vb.z*wb.z + vb.w*wb.w;
        }
        const float isq = 0.17677669529663687f;
        s00*=isq; s01*=isq; s10*=isq; s11*=isq;
        {
            float m = fmaxf(s00, s01);
            float e0 = __expf(s00-m), e1 = __expf(s01-m);
            float p0 = e0/(e0+e1);
            pat[h*4+0] = 0.5f + 0.5f*p0;
            pat[h*4+1] = 0.5f + 0.5f*(1.0f-p0);
        }
        {
            float m = fmaxf(s10, s11);
            float e0 = __expf(s10-m), e1 = __expf(s11-m);
            float p0 = e0/(e0+e1);
            pat[h*4+2] = 0.5f + 0.5f*p0;
            pat[h*4+3] = 0.5f + 0.5f*(1.0f-p0);
        }
    }
    float* dst = g_pat + (size_t)pair*16;
    #pragma unroll
    for (int i=0;i<4;i++)
        *(float4*)(dst + i*4) = make_float4(pat[i*4],pat[i*4+1],pat[i*4+2],pat[i*4+3]);
}

// ---------------- kFB4: fused bf16-split mma.sync GEMM + base epilogue ----------------
// smem: sPat 4KB | Ah 16KB | Al 16KB | Bh 16KB | Bl 16KB = 69632 bytes
#define SMEM_TOT 69632

__device__ __forceinline__ void packrow(uint4 &h4, uint4 &l4, const float* pr){
    unsigned hw[4], lw[4];
    #pragma unroll
    for (int i=0;i<4;i++){
        float v0 = fmaxf(pr[2*i],   0.f);
        float v1 = fmaxf(pr[2*i+1], 0.f);
        __nv_bfloat16 b0 = __float2bfloat16(v0), b1 = __float2bfloat16(v1);
        float r0 = v0 - __bfloat162float(b0), r1 = v1 - __bfloat162float(b1);
        __nv_bfloat16 c0 = __float2bfloat16(r0), c1 = __float2bfloat16(r1);
        hw[i] = (unsigned)__bfloat16_as_ushort(b0) | ((unsigned)__bfloat16_as_ushort(b1) << 16);
        lw[i] = (unsigned)__bfloat16_as_ushort(c0) | ((unsigned)__bfloat16_as_ushort(c1) << 16);
    }
    h4 = make_uint4(hw[0],hw[1],hw[2],hw[3]);
    l4 = make_uint4(lw[0],lw[1],lw[2],lw[3]);
}

__global__ void __launch_bounds__(256, 2) kFB4(){
    extern __shared__ char smem[];
    float* sPat = (float*)smem;
    char* pAh = smem + 4096;
    char* pAl = smem + 4096 + 16384;
    char* pBh = smem + 4096 + 32768;
    char* pBl = smem + 4096 + 49152;
    const uint32_t sb  = smem_u32(smem);
    const uint32_t aAh = sb + 4096, aAl = aAh + 16384, aBh = aAl + 16384, aBl = aBh + 16384;

    const int tid = threadIdx.x, lane = tid & 31, wid = tid >> 5;
    const int p0 = blockIdx.x * PPB;

    // stage pat [64][16]
    {
        int lp0 = tid >> 2, part = tid & 3;
        float4 v = *(const float4*)(g_pat + (size_t)(p0 + lp0)*16 + part*4);
        *(float4*)(sPat + lp0*16 + part*4) = v;
    }

    const int lp = tid >> 2, q4 = tid & 3;
    const int pair = p0 + lp;
    const int a = pair / PV, b = pair % PV;
    const int ca = 2*a, cb = 2*b + 1;
    const float* pEa = g_EW1 + ca*HID;
    const float* pEb = g_EW1 + cb*HID;
    const float* pAa = g_AW1 + (ca*NH)*HID;
    const float* pAb = g_AW1 + (cb*NH)*HID;

    const int wm = wid >> 1, wn = wid & 1;
    float acc[2][8][4];
    #pragma unroll
    for (int i=0;i<2;i++)
        #pragma unroll
        for (int j=0;j<8;j++)
            #pragma unroll
            for (int k=0;k<4;k++) acc[i][j][k] = 0.f;

    __syncthreads();

    for (int c = 0; c < NCHUNK; c++){
        const int kk = c*KCH;

        // ---- stage B hi/lo ([k 64][n 128] bf16, swizzled) ----
        #pragma unroll
        for (int i=0;i<4;i++){
            int lin = tid + i*256;           // 0..1023
            int k = lin >> 4, nq = lin & 15;
            uint4 vh = *(const uint4*)(g_Bh + (kk+k)*DIM + nq*8);
            uint4 vl = *(const uint4*)(g_Bl + (kk+k)*DIM + nq*8);
            uint32_t off = (uint32_t)(k*256 + ((nq ^ (k & 7)) << 4));
            *(uint4*)(pBh + off) = vh;
            *(uint4*)(pBl + off) = vl;
        }

        // ---- compute A fragment (preact->relu->bf16 split), store swizzled ----
        float pv[16];
        #pragma unroll
        for (int i=0;i<16;i++) pv[i] = sPat[lp*16 + i];
        #pragma unroll
        for (int g=0; g<2; g++){
            const int j = kk + q4*16 + g*8;
            float4 e0 = *(const float4*)(pEa + j);
            float4 e1 = *(const float4*)(pEa + j + 4);
            float4 f0 = *(const float4*)(pEb + j);
            float4 f1 = *(const float4*)(pEb + j + 4);
            float pr0[8] = {e0.x,e0.y,e0.z,e0.w,e1.x,e1.y,e1.z,e1.w};
            float pr1[8] = {f0.x,f0.y,f0.z,f0.w,f1.x,f1.y,f1.z,f1.w};
            #pragma unroll
            for (int h=0; h<NH; h++){
                float4 A0 = *(const float4*)(pAa + h*HID + j);
                float4 A1 = *(const float4*)(pAa + h*HID + j + 4);
                float4 B0 = *(const float4*)(pAb + h*HID + j);
                float4 B1 = *(const float4*)(pAb + h*HID + j + 4);
                float aa[8] = {A0.x,A0.y,A0.z,A0.w,A1.x,A1.y,A1.z,A1.w};
                float bb[8] = {B0.x,B0.y,B0.z,B0.w,B1.x,B1.y,B1.z,B1.w};
                float w00 = pv[h*4+0], w01 = pv[h*4+1];
                float w10 = pv[h*4+2], w11 = pv[h*4+3];
                #pragma unroll
                for (int cc=0;cc<8;cc++){
                    pr0[cc] += w00*aa[cc] + w01*bb[cc];
                    pr1[cc] += w10*aa[cc] + w11*bb[cc];
                }
            }
            const int q = q4*2 + g;
            uint4 h4, l4;
            int m0 = 2*lp;
            packrow(h4, l4, pr0);
            uint32_t off0 = (uint32_t)(m0*128 + ((q ^ permA(m0)) << 4));
            *(uint4*)(pAh + off0) = h4; *(uint4*)(pAl + off0) = l4;
            packrow(h4, l4, pr1);
            int m1 = m0 + 1;
            uint32_t off1 = (uint32_t)(m1*128 + ((q ^ permA(m1)) << 4));
            *(uint4*)(pAh + off1) = h4; *(uint4*)(pAl + off1) = l4;
        }

        __syncthreads();

        // ---- MMA phase ----
        #pragma unroll
        for (int ks=0; ks<4; ks++){
            uint32_t ah[2][4], al[2][4];
            #pragma unroll
            for (int mf=0; mf<2; mf++){
                int r  = wm*32 + mf*16 + (lane & 15);
                int kq = ks*2 + (lane >> 4);
                uint32_t off = (uint32_t)(r*128 + ((kq ^ permA(r)) << 4));
                ldsm4(ah[mf], aAh + off);
                ldsm4(al[mf], aAl + off);
            }
            int kr = ks*16 + (lane & 15);
            #pragma unroll
            for (int nb=0; nb<4; nb++){
                int nq = wn*8 + nb*2 + (lane >> 4);
                uint32_t off = (uint32_t)(kr*256 + ((nq ^ (kr & 7)) << 4));
                uint32_t bh[4], bl[4];
                ldsm4t(bh, aBh + off);
                ldsm4t(bl, aBl + off);
                #pragma unroll
                for (int mf=0; mf<2; mf++){
                    mma16816(acc[mf][nb*2],   ah[mf], bh[0], bh[1]);
                    mma16816(acc[mf][nb*2+1], ah[mf], bh[2], bh[3]);
                    mma16816(acc[mf][nb*2],   al[mf], bh[0], bh[1]);
                    mma16816(acc[mf][nb*2+1], al[mf], bh[2], bh[3]);
                    mma16816(acc[mf][nb*2],   ah[mf], bl[0], bl[1]);
                    mma16816(acc[mf][nb*2+1], ah[mf], bl[2], bl[3]);
                }
            }
        }
        __syncthreads();
    }

    // ---- epilogue: base = EU + sum_h pat*AU, add acc, write table ----
    #pragma unroll
    for (int mf=0; mf<2; mf++){
        #pragma unroll
        for (int hh=0; hh<2; hh++){
            int row = wm*32 + mf*16 + (lane >> 2) + hh*8;
            int rlp = row >> 1, qi = row & 1;
            int rpair = p0 + rlp;
            int ra = rpair / PV, rb = rpair % PV;
            int rca = 2*ra, rcb = 2*rb + 1;
            int cq = qi ? rcb : rca;
            int gm = p0*2 + row;
            float wA[4], wB[4];
            #pragma unroll
            for (int h=0; h<NH; h++){
                wA[h] = sPat[rlp*16 + h*4 + qi*2 + 0];
                wB[h] = sPat[rlp*16 + h*4 + qi*2 + 1];
            }
            const float* eu  = g_EU + cq*PVP;
            const float* aua = g_AU + (rca*NH)*PVP;
            const float* aub = g_AU + (rcb*NH)*PVP;
            #pragma unroll
            for (int nf=0; nf<8; nf++){
                int n = wn*64 + nf*8 + (lane & 3)*2;
                float2 base = *(const float2*)(eu + n);
                #pragma unroll
                for (int h=0; h<NH; h++){
                    float2 va = *(const float2*)(aua + h*PVP + n);
                    float2 vb = *(const float2*)(aub + h*PVP + n);
                    base.x += wA[h]*va.x + wB[h]*vb.x;
                    base.y += wA[h]*va.y + wB[h]*vb.y;
                }
                if (gm < NTOK){
                    float c0 = acc[mf][nf][hh*2+0] + base.x;
                    float c1 = acc[mf][nf][hh*2+1] + base.y;
                    float* ts = g_table + (size_t)gm*PV;
                    if (n   < PV) ts[n]   = c0;
                    if (n+1 < PV) ts[n+1] = c1;
                }
            }
        }
    }
}

// ---------------- G: gather ----------------
__global__ void kG(const int* __restrict__ x, float* __restrict__ out, int B){
    int ex = blockIdx.x*8 + (threadIdx.x >> 5);
    if (ex >= B) return;
    int lane = threadIdx.x & 31;
    int a = x[ex*2], b = x[ex*2+1];
    const float2* src = (const float2*)(g_table + (size_t)(a*PV + b)*226);
    float2* dst = (float2*)(out + (size_t)ex*226);
    #pragma unroll
    for (int i=0;i<4;i++){
        int idx = lane + i*32;
        if (idx < PV) dst[idx] = src[idx];
    }
}

// ---------------- launch ----------------
extern "C" void kernel_launch(void* const* d_in, const int* in_sizes, int n_in,
                              void* d_out, int out_size){
    const int*   x   = (const int*)  d_in[0];
    const float* tok = (const float*)d_in[1];
    const float* pos = (const float*)d_in[2];
    const float* WQ  = (const float*)d_in[3];
    const float* WK  = (const float*)d_in[4];
    const float* WV  = (const float*)d_in[5];
    const float* WO  = (const float*)d_in[6];
    const float* W1  = (const float*)d_in[7];
    const float* b1  = (const float*)d_in[8];
    const float* W2  = (const float*)d_in[9];
    const float* b2  = (const float*)d_in[10];
    const float* WU  = (const float*)d_in[11];
    float* out = (float*)d_out;
    const int B = in_sizes[0] / 2;

    cudaFuncSetAttribute(kFB4, cudaFuncAttributeMaxDynamicSharedMemorySize, SMEM_TOT);

    kA1<<<569, 256>>>(WO, W1, W2, b2, WU);
    kA2<<<NCOMBO, 256>>>(tok, pos, WQ, WK, WV, W1, b1, WU);
    kPat<<<(NPAIR + 255)/256, 256>>>();
    kFB4<<<GEMM_GRID, 256, SMEM_TOT>>>();
    kG<<<(B + 7)/8, 256>>>(x, out, B);
}

// round 5
// speedup vs baseline: 1.6117x; 1.6117x over previous
#include <cuda_runtime.h>
#include <cuda_fp16.h>
#include <cstdint>

#define PV   113
#define PVP  128
#define DIM  128
#define NH   4
#define DHD  32
#define HID  512
#define NCOMBO 226
#define NPAIR (PV*PV)      // 12769
#define NTOK  (NPAIR*2)    // 25538
#define PPB   64           // pairs per GEMM CTA (128 rows)
#define KCH   64
#define NCHUNK (HID/KCH)   // 8
#define GEMM_GRID ((NPAIR + PPB - 1)/PPB)   // 200

// ---------------- device scratch (zero-initialized) ----------------
__device__ __align__(16) float g_OW1[NH*DHD*HID];
__device__ __align__(16) float g_OU [NH*DHD*PV];
__device__ __align__(16) float g_b2u[PV];
__device__ __align__(16) float g_qk [2*NCOMBO*DIM + 4*DIM];   // padded
__device__ __align__(16) float g_EW1[(NCOMBO+2)*HID];         // padded (zeros)
__device__ __align__(16) float g_EU [(NCOMBO+2)*PVP];         // stride 128, padded
__device__ __align__(16) float g_AW1[(NCOMBO+2)*NH*HID];      // padded (zeros)
__device__ __align__(16) float g_AU [(NCOMBO+2)*NH*PVP];      // stride 128, padded
__device__ __align__(16) __half g_Bh[HID*DIM];                // [k][n] W2U hi (fp16)
__device__ __align__(16) __half g_Bl[HID*DIM];                // [k][n] W2U lo (fp16)
__device__ __align__(16) float g_table[(size_t)NTOK*PV];

// ---------------- helpers ----------------
__device__ __forceinline__ uint32_t smem_u32(const void* p){
    uint32_t a;
    asm("{ .reg .u64 t; cvta.to.shared.u64 t, %1; cvt.u32.u64 %0, t; }" : "=r"(a) : "l"(p));
    return a;
}
__device__ __forceinline__ void cpa16(uint32_t dst, const void* src){
    asm volatile("cp.async.cg.shared.global [%0], [%1], 16;" :: "r"(dst), "l"(src));
}
__device__ __forceinline__ void ldsm4(uint32_t* r, uint32_t a){
    asm volatile("ldmatrix.sync.aligned.m8n8.x4.shared.b16 {%0,%1,%2,%3}, [%4];"
        : "=r"(r[0]),"=r"(r[1]),"=r"(r[2]),"=r"(r[3]) : "r"(a));
}
__device__ __forceinline__ void ldsm4t(uint32_t* r, uint32_t a){
    asm volatile("ldmatrix.sync.aligned.m8n8.x4.trans.shared.b16 {%0,%1,%2,%3}, [%4];"
        : "=r"(r[0]),"=r"(r[1]),"=r"(r[2]),"=r"(r[3]) : "r"(a));
}
__device__ __forceinline__ void mma16816(float* c, const uint32_t* a, uint32_t b0, uint32_t b1){
    asm volatile("mma.sync.aligned.m16n8k16.row.col.f32.f16.f16.f32 "
        "{%0,%1,%2,%3}, {%4,%5,%6,%7}, {%8,%9}, {%0,%1,%2,%3};"
        : "+f"(c[0]),"+f"(c[1]),"+f"(c[2]),"+f"(c[3])
        : "r"(a[0]),"r"(a[1]),"r"(a[2]),"r"(a[3]), "r"(b0),"r"(b1));
}
__device__ __forceinline__ int permA(int m){ int t = m & 7; return (t>>1) | ((t&1)<<2); }

// ---------------- A1: fold weights (+ fp16-split B) ----------------
__global__ void kA1(const float* __restrict__ WO, const float* __restrict__ W1,
                    const float* __restrict__ W2, const float* __restrict__ b2,
                    const float* __restrict__ WU){
    int t = blockIdx.x*256 + threadIdx.x;
    if (t < 65536) {
        int j = t & 511, hi = t >> 9;
        const float* wo = WO + hi*DIM;
        float s = 0.f;
        #pragma unroll 8
        for (int d=0; d<DIM; d++) s += wo[d]*W1[d*HID + j];
        g_OW1[t] = s;
    } else if (t < 80000) {
        int u = t - 65536; int p = u % PV; int hi = u / PV;
        const float* wo = WO + hi*DIM; const float* wu = WU + p*DIM;
        float s = 0.f;
        #pragma unroll 8
        for (int d=0; d<DIM; d++) s += wo[d]*wu[d];
        g_OU[u] = s;
    } else if (t < 145536) {
        int u = t - 80000; int n = u & 127; int j = u >> 7;
        float s = 0.f;
        if (n < PV) {
            const float* w2 = W2 + j*DIM; const float* wu = WU + n*DIM;
            #pragma unroll 8
            for (int d=0; d<DIM; d++) s += w2[d]*wu[d];
        }
        __half hh = __float2half_rn(s);
        g_Bh[u] = hh;                         // [j][n] = [k][n]
        g_Bl[u] = __float2half_rn(s - __half2float(hh));
    } else if (t < 145649) {
        int p = t - 145536;
        const float* wu = WU + p*DIM;
        float s = 0.f;
        #pragma unroll 8
        for (int d=0; d<DIM; d++) s += b2[d]*wu[d];
        g_b2u[p] = s;
    }
}

// ---------------- A2: per-combo tables ----------------
__global__ void kA2(const float* __restrict__ tok_emb, const float* __restrict__ pos_emb,
                    const float* __restrict__ WQ, const float* __restrict__ WK,
                    const float* __restrict__ WV, const float* __restrict__ W1,
                    const float* __restrict__ b1, const float* __restrict__ WU){
    __shared__ float e[DIM];
    __shared__ float vv[DIM];
    const int c = blockIdx.x;
    const int tk = c >> 1, pos = c & 1;
    const int tid = threadIdx.x;
    if (tid < DIM) e[tid] = tok_emb[tk*DIM + tid] + pos_emb[pos*DIM + tid];
    __syncthreads();

    for (int o = tid; o < 384; o += 256) {
        int sel = o >> 7; int idx = o & 127;
        const float* W = (sel==0) ? WQ : ((sel==1) ? WK : WV);
        int h = idx >> 5, i = idx & 31;
        float s = 0.f;
        #pragma unroll 8
        for (int d=0; d<DIM; d++) s += e[d]*W[(h*DIM + d)*DHD + i];
        if (sel < 2) g_qk[(sel*NCOMBO + c)*DIM + idx] = s;
        else         vv[idx] = s;
    }
    __syncthreads();

    for (int j = tid; j < HID; j += 256) {
        float s = b1[j];
        #pragma unroll 8
        for (int d=0; d<DIM; d++) s += e[d]*W1[d*HID + j];
        g_EW1[c*HID + j] = s;
    }
    if (tid < PV) {
        const float* wu = WU + tid*DIM;
        float s = g_b2u[tid];
        #pragma unroll 8
        for (int d=0; d<DIM; d++) s += e[d]*wu[d];
        g_EU[c*PVP + tid] = s;
    }
    for (int o = tid; o < NH*HID; o += 256) {
        int h = o >> 9; int j = o & 511;
        float s = 0.f;
        #pragma unroll
        for (int i=0; i<DHD; i++) s += vv[h*DHD + i]*g_OW1[(h*DHD + i)*HID + j];
        g_AW1[(c*NH + h)*HID + j] = s;
    }
    for (int o = tid; o < NH*PV; o += 256) {
        int h = o / PV; int p = o % PV;
        float s = 0.f;
        #pragma unroll
        for (int i=0; i<DHD; i++) s += vv[h*DHD + i]*g_OU[(h*DHD + i)*PV + p];
        g_AU[(c*NH + h)*PVP + p] = s;
    }
}

// ---------------- kFB5: fused pat + preact/relu(fp16) + 2-term mma GEMM ----------------
// smem: sPat 4KB | buf0 {A 16KB, Bh 16KB, Bl 16KB} | buf1 {...} = 102400 B
#define BUFSZ 49152
#define SMEM_TOT (4096 + 2*BUFSZ)

__device__ __forceinline__ uint4 packrow_h(const float* pr){
    uint32_t w[4];
    #pragma unroll
    for (int i=0;i<4;i++){
        __half h0 = __float2half_rn(fmaxf(pr[2*i],   0.f));
        __half h1 = __float2half_rn(fmaxf(pr[2*i+1], 0.f));
        w[i] = (uint32_t)__half_as_ushort(h0) | ((uint32_t)__half_as_ushort(h1) << 16);
    }
    return make_uint4(w[0],w[1],w[2],w[3]);
}

__global__ void __launch_bounds__(256, 2) kFB5(){
    extern __shared__ char smem[];
    float* sPat = (float*)smem;
    const uint32_t sb = smem_u32(smem);
    const int tid = threadIdx.x, lane = tid & 31, wid = tid >> 5;
    const int p0 = blockIdx.x * PPB;

    // ---- in-CTA attention pattern: 2 pairs per thread (64 pairs x 4 heads x 2 qi) ----
    {
        const float isq = 0.17677669529663687f;
        #pragma unroll
        for (int r=0; r<2; r++){
            int pp = (tid >> 3) + r*32;
            int h  = (tid >> 1) & 3;
            int qi = tid & 1;
            int pr = p0 + pp;
            int a0 = pr / PV, b0 = pr % PV;
            int ca0 = 2*a0, cb0 = 2*b0 + 1;
            int cq = qi ? cb0 : ca0;
            const float* q  = g_qk + (0*NCOMBO + cq )*DIM + h*DHD;
            const float* k0 = g_qk + (1*NCOMBO + ca0)*DIM + h*DHD;
            const float* k1 = g_qk + (1*NCOMBO + cb0)*DIM + h*DHD;
            float s0=0.f, s1=0.f;
            #pragma unroll
            for (int i=0;i<DHD;i++){ float qv = q[i]; s0 += qv*k0[i]; s1 += qv*k1[i]; }
            s0 *= isq; s1 *= isq;
            float m = fmaxf(s0, s1);
            float e0 = __expf(s0-m), e1 = __expf(s1-m);
            float p = e0/(e0+e1);
            sPat[pp*16 + h*4 + qi*2 + 0] = 0.5f + 0.5f*p;
            sPat[pp*16 + h*4 + qi*2 + 1] = 0.5f + 0.5f*(1.0f-p);
        }
    }
    __syncthreads();

    // per-thread A-compute state: thread = (pair lp 0..63, quarter q4 0..3)
    const int lp = tid >> 2, q4 = tid & 3;
    const int pair = p0 + lp;
    const int a = pair / PV, b = pair % PV;
    const int ca = 2*a, cb = 2*b + 1;
    const float* pEa = g_EW1 + ca*HID;
    const float* pEb = g_EW1 + cb*HID;
    const float* pAa = g_AW1 + (ca*NH)*HID;
    const float* pAb = g_AW1 + (cb*NH)*HID;
    float pv[16];
    #pragma unroll
    for (int i=0;i<16;i++) pv[i] = sPat[lp*16 + i];

    const int wm = wid >> 1, wn = wid & 1;
    float acc[2][8][4];
    #pragma unroll
    for (int i=0;i<2;i++)
        #pragma unroll
        for (int j=0;j<8;j++)
            #pragma unroll
            for (int k=0;k<4;k++) acc[i][j][k] = 0.f;

    // ---------- staging routine (chunk c into buffer c&1) ----------
    auto stage = [&](int c){
        const int buf = c & 1;
        char* pA  = smem + 4096 + buf*BUFSZ;
        const uint32_t aBh = sb + 4096 + buf*BUFSZ + 16384;
        const uint32_t aBl = aBh + 16384;
        const int kk = c*KCH;
        // B hi/lo via cp.async (swizzled [k][n])
        #pragma unroll
        for (int i=0;i<4;i++){
            int lin = tid + i*256;           // 0..1023
            int k = lin >> 4, nq = lin & 15;
            uint32_t off = (uint32_t)(k*256 + ((nq ^ (k & 7)) << 4));
            cpa16(aBh + off, g_Bh + (kk+k)*DIM + nq*8);
            cpa16(aBl + off, g_Bl + (kk+k)*DIM + nq*8);
        }
        asm volatile("cp.async.commit_group;");
        // A fragment: preact -> relu -> fp16, swizzled store
        #pragma unroll
        for (int g=0; g<2; g++){
            const int j = kk + q4*16 + g*8;
            float4 e0 = *(const float4*)(pEa + j);
            float4 e1 = *(const float4*)(pEa + j + 4);
            float4 f0 = *(const float4*)(pEb + j);
            float4 f1 = *(const float4*)(pEb + j + 4);
            float pr0[8] = {e0.x,e0.y,e0.z,e0.w,e1.x,e1.y,e1.z,e1.w};
            float pr1[8] = {f0.x,f0.y,f0.z,f0.w,f1.x,f1.y,f1.z,f1.w};
            #pragma unroll
            for (int h=0; h<NH; h++){
                float4 A0 = *(const float4*)(pAa + h*HID + j);
                float4 A1 = *(const float4*)(pAa + h*HID + j + 4);
                float4 B0 = *(const float4*)(pAb + h*HID + j);
                float4 B1 = *(const float4*)(pAb + h*HID + j + 4);
                float aa[8] = {A0.x,A0.y,A0.z,A0.w,A1.x,A1.y,A1.z,A1.w};
                float bb[8] = {B0.x,B0.y,B0.z,B0.w,B1.x,B1.y,B1.z,B1.w};
                float w00 = pv[h*4+0], w01 = pv[h*4+1];
                float w10 = pv[h*4+2], w11 = pv[h*4+3];
                #pragma unroll
                for (int cc=0;cc<8;cc++){
                    pr0[cc] += w00*aa[cc] + w01*bb[cc];
                    pr1[cc] += w10*aa[cc] + w11*bb[cc];
                }
            }
            const int q = q4*2 + g;
            int m0 = 2*lp, m1 = m0 + 1;
            uint32_t off0 = (uint32_t)(m0*128 + ((q ^ permA(m0)) << 4));
            uint32_t off1 = (uint32_t)(m1*128 + ((q ^ permA(m1)) << 4));
            *(uint4*)(pA + off0) = packrow_h(pr0);
            *(uint4*)(pA + off1) = packrow_h(pr1);
        }
    };

    // ---------- pipelined main loop ----------
    stage(0);
    asm volatile("cp.async.wait_group 0;");
    __syncthreads();

    for (int c = 0; c < NCHUNK; c++){
        if (c + 1 < NCHUNK) stage(c + 1);     // overlaps with MMA(c) below

        const int buf = c & 1;
        const uint32_t aA  = sb + 4096 + buf*BUFSZ;
        const uint32_t aBh = aA + 16384;
        const uint32_t aBl = aA + 32768;

        #pragma unroll
        for (int ks=0; ks<4; ks++){
            uint32_t ah[2][4];
            #pragma unroll
            for (int mf=0; mf<2; mf++){
                int r  = wm*32 + mf*16 + (lane & 15);
                int kq = ks*2 + (lane >> 4);
                uint32_t off = (uint32_t)(r*128 + ((kq ^ permA(r)) << 4));
                ldsm4(ah[mf], aA + off);
            }
            int kr = ks*16 + (lane & 15);
            #pragma unroll
            for (int nb=0; nb<4; nb++){
                int nq = wn*8 + nb*2 + (lane >> 4);
                uint32_t off = (uint32_t)(kr*256 + ((nq ^ (kr & 7)) << 4));
                uint32_t bh[4], bl[4];
                ldsm4t(bh, aBh + off);
                ldsm4t(bl, aBl + off);
                #pragma unroll
                for (int mf=0; mf<2; mf++){
                    mma16816(acc[mf][nb*2],   ah[mf], bh[0], bh[1]);
                    mma16816(acc[mf][nb*2+1], ah[mf], bh[2], bh[3]);
                    mma16816(acc[mf][nb*2],   ah[mf], bl[0], bl[1]);
                    mma16816(acc[mf][nb*2+1], ah[mf], bl[2], bl[3]);
                }
            }
        }
        asm volatile("cp.async.wait_group 0;");
        __syncthreads();
    }

    // ---- epilogue: base = EU + sum_h pat*AU, add acc, write table ----
    #pragma unroll
    for (int mf=0; mf<2; mf++){
        #pragma unroll
        for (int hh=0; hh<2; hh++){
            int row = wm*32 + mf*16 + (lane >> 2) + hh*8;
            int rlp = row >> 1, qi = row & 1;
            int rpair = p0 + rlp;
            int ra = rpair / PV, rb = rpair % PV;
            int rca = 2*ra, rcb = 2*rb + 1;
            int cq = qi ? rcb : rca;
            int gm = p0*2 + row;
            float wA[4], wB[4];
            #pragma unroll
            for (int h=0; h<NH; h++){
                wA[h] = sPat[rlp*16 + h*4 + qi*2 + 0];
                wB[h] = sPat[rlp*16 + h*4 + qi*2 + 1];
            }
            const float* eu  = g_EU + cq*PVP;
            const float* aua = g_AU + (rca*NH)*PVP;
            const float* aub = g_AU + (rcb*NH)*PVP;
            #pragma unroll
            for (int nf=0; nf<8; nf++){
                int n = wn*64 + nf*8 + (lane & 3)*2;
                float2 base = *(const float2*)(eu + n);
                #pragma unroll
                for (int h=0; h<NH; h++){
                    float2 va = *(const float2*)(aua + h*PVP + n);
                    float2 vb = *(const float2*)(aub + h*PVP + n);
                    base.x += wA[h]*va.x + wB[h]*vb.x;
                    base.y += wA[h]*va.y + wB[h]*vb.y;
                }
                if (gm < NTOK){
                    float c0 = acc[mf][nf][hh*2+0] + base.x;
                    float c1 = acc[mf][nf][hh*2+1] + base.y;
                    float* ts = g_table + (size_t)gm*PV;
                    if (n   < PV) ts[n]   = c0;
                    if (n+1 < PV) ts[n+1] = c1;
                }
            }
        }
    }
}

// ---------------- G: gather ----------------
__global__ void kG(const int* __restrict__ x, float* __restrict__ out, int B){
    int ex = blockIdx.x*8 + (threadIdx.x >> 5);
    if (ex >= B) return;
    int lane = threadIdx.x & 31;
    int a = x[ex*2], b = x[ex*2+1];
    const float2* src = (const float2*)(g_table + (size_t)(a*PV + b)*226);
    float2* dst = (float2*)(out + (size_t)ex*226);
    #pragma unroll
    for (int i=0;i<4;i++){
        int idx = lane + i*32;
        if (idx < PV) dst[idx] = src[idx];
    }
}

// ---------------- launch ----------------
extern "C" void kernel_launch(void* const* d_in, const int* in_sizes, int n_in,
                              void* d_out, int out_size){
    const int*   x   = (const int*)  d_in[0];
    const float* tok = (const float*)d_in[1];
    const float* pos = (const float*)d_in[2];
    const float* WQ  = (const float*)d_in[3];
    const float* WK  = (const float*)d_in[4];
    const float* WV  = (const float*)d_in[5];
    const float* WO  = (const float*)d_in[6];
    const float* W1  = (const float*)d_in[7];
    const float* b1  = (const float*)d_in[8];
    const float* W2  = (const float*)d_in[9];
    const float* b2  = (const float*)d_in[10];
    const float* WU  = (const float*)d_in[11];
    float* out = (float*)d_out;
    const int B = in_sizes[0] / 2;

    cudaFuncSetAttribute(kFB5, cudaFuncAttributeMaxDynamicSharedMemorySize, SMEM_TOT);

    kA1<<<569, 256>>>(WO, W1, W2, b2, WU);
    kA2<<<NCOMBO, 256>>>(tok, pos, WQ, WK, WV, W1, b1, WU);
    kFB5<<<GEMM_GRID, 256, SMEM_TOT>>>();
    kG<<<(B + 7)/8, 256>>>(x, out, B);
}

// round 6
// speedup vs baseline: 1.7330x; 1.0752x over previous
#include <cuda_runtime.h>
#include <cuda_fp16.h>
#include <cstdint>

#define PV   113
#define PVP  128
#define DIM  128
#define NH   4
#define DHD  32
#define HID  512
#define NCOMBO 226
#define NPAIR (PV*PV)      // 12769
#define NTOK  (NPAIR*2)    // 25538
#define PPB   64           // pairs per GEMM CTA (128 rows)
#define KCH   64
#define NCHUNK (HID/KCH)   // 8
#define GEMM_GRID ((NPAIR + PPB - 1)/PPB)   // 200

// ---------------- device scratch (zero-initialized) ----------------
__device__ __align__(16) float g_OW1[NH*DHD*HID];
__device__ __align__(16) float g_OU [NH*DHD*PV];
__device__ __align__(16) float g_b2u[PV];
__device__ __align__(16) float g_qk [2*NCOMBO*DIM + 4*DIM];   // padded
__device__ __align__(16) float g_EW1[(NCOMBO+2)*HID];         // padded (zeros)
__device__ __align__(16) float g_EU [(NCOMBO+2)*PVP];         // stride 128, padded
__device__ __align__(16) float g_AW1[(NCOMBO+2)*NH*HID];      // padded (zeros)
__device__ __align__(16) float g_AU [(NCOMBO+2)*NH*PVP];      // stride 128, padded
__device__ __align__(16) __half g_Bh[HID*DIM];                // [k][n] W2U (fp16)
__device__ __align__(16) float g_table[(size_t)NTOK*PV];

// ---------------- helpers ----------------
__device__ __forceinline__ uint32_t smem_u32(const void* p){
    uint32_t a;
    asm("{ .reg .u64 t; cvta.to.shared.u64 t, %1; cvt.u32.u64 %0, t; }" : "=r"(a) : "l"(p));
    return a;
}
__device__ __forceinline__ void cpa16(uint32_t dst, const void* src){
    asm volatile("cp.async.cg.shared.global [%0], [%1], 16;" :: "r"(dst), "l"(src));
}
__device__ __forceinline__ void ldsm4(uint32_t* r, uint32_t a){
    asm volatile("ldmatrix.sync.aligned.m8n8.x4.shared.b16 {%0,%1,%2,%3}, [%4];"
        : "=r"(r[0]),"=r"(r[1]),"=r"(r[2]),"=r"(r[3]) : "r"(a));
}
__device__ __forceinline__ void ldsm4t(uint32_t* r, uint32_t a){
    asm volatile("ldmatrix.sync.aligned.m8n8.x4.trans.shared.b16 {%0,%1,%2,%3}, [%4];"
        : "=r"(r[0]),"=r"(r[1]),"=r"(r[2]),"=r"(r[3]) : "r"(a));
}
__device__ __forceinline__ void mma16816(float* c, const uint32_t* a, uint32_t b0, uint32_t b1){
    asm volatile("mma.sync.aligned.m16n8k16.row.col.f32.f16.f16.f32 "
        "{%0,%1,%2,%3}, {%4,%5,%6,%7}, {%8,%9}, {%0,%1,%2,%3};"
        : "+f"(c[0]),"+f"(c[1]),"+f"(c[2]),"+f"(c[3])
        : "r"(a[0]),"r"(a[1]),"r"(a[2]),"r"(a[3]), "r"(b0),"r"(b1));
}
__device__ __forceinline__ int permA(int m){ int t = m & 7; return (t>>1) | ((t&1)<<2); }

// ---------------- A1: fold weights (+ fp16 B) ----------------
__global__ void kA1(const float* __restrict__ WO, const float* __restrict__ W1,
                    const float* __restrict__ W2, const float* __restrict__ b2,
                    const float* __restrict__ WU){
    int t = blockIdx.x*256 + threadIdx.x;
    if (t < 65536) {
        int j = t & 511, hi = t >> 9;
        const float* wo = WO + hi*DIM;
        float s = 0.f;
        #pragma unroll 8
        for (int d=0; d<DIM; d++) s += wo[d]*W1[d*HID + j];
        g_OW1[t] = s;
    } else if (t < 80000) {
        int u = t - 65536; int p = u % PV; int hi = u / PV;
        const float* wo = WO + hi*DIM; const float* wu = WU + p*DIM;
        float s = 0.f;
        #pragma unroll 8
        for (int d=0; d<DIM; d++) s += wo[d]*wu[d];
        g_OU[u] = s;
    } else if (t < 145536) {
        int u = t - 80000; int n = u & 127; int j = u >> 7;
        float s = 0.f;
        if (n < PV) {
            const float* w2 = W2 + j*DIM; const float* wu = WU + n*DIM;
            #pragma unroll 8
            for (int d=0; d<DIM; d++) s += w2[d]*wu[d];
        }
        g_Bh[u] = __float2half_rn(s);         // [j][n] = [k][n]
    } else if (t < 145649) {
        int p = t - 145536;
        const float* wu = WU + p*DIM;
        float s = 0.f;
        #pragma unroll 8
        for (int d=0; d<DIM; d++) s += b2[d]*wu[d];
        g_b2u[p] = s;
    }
}

// ---------------- A2: per-combo tables ----------------
__global__ void kA2(const float* __restrict__ tok_emb, const float* __restrict__ pos_emb,
                    const float* __restrict__ WQ, const float* __restrict__ WK,
                    const float* __restrict__ WV, const float* __restrict__ W1,
                    const float* __restrict__ b1, const float* __restrict__ WU){
    __shared__ float e[DIM];
    __shared__ float vv[DIM];
    const int c = blockIdx.x;
    const int tk = c >> 1, pos = c & 1;
    const int tid = threadIdx.x;
    if (tid < DIM) e[tid] = tok_emb[tk*DIM + tid] + pos_emb[pos*DIM + tid];
    __syncthreads();

    for (int o = tid; o < 384; o += 256) {
        int sel = o >> 7; int idx = o & 127;
        const float* W = (sel==0) ? WQ : ((sel==1) ? WK : WV);
        int h = idx >> 5, i = idx & 31;
        float s = 0.f;
        #pragma unroll 8
        for (int d=0; d<DIM; d++) s += e[d]*W[(h*DIM + d)*DHD + i];
        if (sel < 2) g_qk[(sel*NCOMBO + c)*DIM + idx] = s;
        else         vv[idx] = s;
    }
    __syncthreads();

    for (int j = tid; j < HID; j += 256) {
        float s = b1[j];
        #pragma unroll 8
        for (int d=0; d<DIM; d++) s += e[d]*W1[d*HID + j];
        g_EW1[c*HID + j] = s;
    }
    if (tid < PV) {
        const float* wu = WU + tid*DIM;
        float s = g_b2u[tid];
        #pragma unroll 8
        for (int d=0; d<DIM; d++) s += e[d]*wu[d];
        g_EU[c*PVP + tid] = s;
    }
    for (int o = tid; o < NH*HID; o += 256) {
        int h = o >> 9; int j = o & 511;
        float s = 0.f;
        #pragma unroll
        for (int i=0; i<DHD; i++) s += vv[h*DHD + i]*g_OW1[(h*DHD + i)*HID + j];
        g_AW1[(c*NH + h)*HID + j] = s;
    }
    for (int o = tid; o < NH*PV; o += 256) {
        int h = o / PV; int p = o % PV;
        float s = 0.f;
        #pragma unroll
        for (int i=0; i<DHD; i++) s += vv[h*DHD + i]*g_OU[(h*DHD + i)*PV + p];
        g_AU[(c*NH + h)*PVP + p] = s;
    }
}

// ---------------- kFB6: fused pat + preact/relu(fp16) + 1-term-B mma GEMM ----------------
// smem: sPat 4KB | buf0 {A 16KB, B 16KB} | buf1 {...} = 69632 B
#define BUFSZ 32768
#define SMEM_TOT (4096 + 2*BUFSZ)

__device__ __forceinline__ uint4 packrow_h(const float* pr){
    uint32_t w[4];
    #pragma unroll
    for (int i=0;i<4;i++){
        __half h0 = __float2half_rn(fmaxf(pr[2*i],   0.f));
        __half h1 = __float2half_rn(fmaxf(pr[2*i+1], 0.f));
        w[i] = (uint32_t)__half_as_ushort(h0) | ((uint32_t)__half_as_ushort(h1) << 16);
    }
    return make_uint4(w[0],w[1],w[2],w[3]);
}

__global__ void __launch_bounds__(256, 2) kFB6(){
    extern __shared__ char smem[];
    float* sPat = (float*)smem;
    const uint32_t sb = smem_u32(smem);
    const int tid = threadIdx.x, lane = tid & 31, wid = tid >> 5;
    const int p0 = blockIdx.x * PPB;

    // ---- in-CTA attention pattern ----
    {
        const float isq = 0.17677669529663687f;
        #pragma unroll
        for (int r=0; r<2; r++){
            int pp = (tid >> 3) + r*32;
            int h  = (tid >> 1) & 3;
            int qi = tid & 1;
            int pr = p0 + pp;
            int a0 = pr / PV, b0 = pr % PV;
            int ca0 = 2*a0, cb0 = 2*b0 + 1;
            int cq = qi ? cb0 : ca0;
            const float* q  = g_qk + (0*NCOMBO + cq )*DIM + h*DHD;
            const float* k0 = g_qk + (1*NCOMBO + ca0)*DIM + h*DHD;
            const float* k1 = g_qk + (1*NCOMBO + cb0)*DIM + h*DHD;
            float s0=0.f, s1=0.f;
            #pragma unroll
            for (int i=0;i<DHD;i++){ float qv = q[i]; s0 += qv*k0[i]; s1 += qv*k1[i]; }
            s0 *= isq; s1 *= isq;
            float m = fmaxf(s0, s1);
            float e0 = __expf(s0-m), e1 = __expf(s1-m);
            float p = e0/(e0+e1);
            sPat[pp*16 + h*4 + qi*2 + 0] = 0.5f + 0.5f*p;
            sPat[pp*16 + h*4 + qi*2 + 1] = 0.5f + 0.5f*(1.0f-p);
        }
    }
    __syncthreads();

    // per-thread A-compute state
    const int lp = tid >> 2, q4 = tid & 3;
    const int pair = p0 + lp;
    const int a = pair / PV, b = pair % PV;
    const int ca = 2*a, cb = 2*b + 1;
    const float* pEa = g_EW1 + ca*HID;
    const float* pEb = g_EW1 + cb*HID;
    const float* pAa = g_AW1 + (ca*NH)*HID;
    const float* pAb = g_AW1 + (cb*NH)*HID;
    float pv[16];
    #pragma unroll
    for (int i=0;i<16;i++) pv[i] = sPat[lp*16 + i];

    const int wm = wid >> 1, wn = wid & 1;
    float acc[2][8][4];
    #pragma unroll
    for (int i=0;i<2;i++)
        #pragma unroll
        for (int j=0;j<8;j++)
            #pragma unroll
            for (int k=0;k<4;k++) acc[i][j][k] = 0.f;

    // ---------- staging routine (chunk c into buffer c&1) ----------
    auto stage = [&](int c){
        const int buf = c & 1;
        char* pA  = smem + 4096 + buf*BUFSZ;
        const uint32_t aB = sb + 4096 + buf*BUFSZ + 16384;
        const int kk = c*KCH;
        // B via cp.async (swizzled [k][n])
        #pragma unroll
        for (int i=0;i<4;i++){
            int lin = tid + i*256;           // 0..1023
            int k = lin >> 4, nq = lin & 15;
            uint32_t off = (uint32_t)(k*256 + ((nq ^ (k & 7)) << 4));
            cpa16(aB + off, g_Bh + (kk+k)*DIM + nq*8);
        }
        asm volatile("cp.async.commit_group;");
        // A fragment: preact -> relu -> fp16, swizzled store
        #pragma unroll
        for (int g=0; g<2; g++){
            const int j = kk + q4*16 + g*8;
            float4 e0 = *(const float4*)(pEa + j);
            float4 e1 = *(const float4*)(pEa + j + 4);
            float4 f0 = *(const float4*)(pEb + j);
            float4 f1 = *(const float4*)(pEb + j + 4);
            float pr0[8] = {e0.x,e0.y,e0.z,e0.w,e1.x,e1.y,e1.z,e1.w};
            float pr1[8] = {f0.x,f0.y,f0.z,f0.w,f1.x,f1.y,f1.z,f1.w};
            #pragma unroll
            for (int h=0; h<NH; h++){
                float4 A0 = *(const float4*)(pAa + h*HID + j);
                float4 A1 = *(const float4*)(pAa + h*HID + j + 4);
                float4 B0 = *(const float4*)(pAb + h*HID + j);
                float4 B1 = *(const float4*)(pAb + h*HID + j + 4);
                float aa[8] = {A0.x,A0.y,A0.z,A0.w,A1.x,A1.y,A1.z,A1.w};
                float bb[8] = {B0.x,B0.y,B0.z,B0.w,B1.x,B1.y,B1.z,B1.w};
                float w00 = pv[h*4+0], w01 = pv[h*4+1];
                float w10 = pv[h*4+2], w11 = pv[h*4+3];
                #pragma unroll
                for (int cc=0;cc<8;cc++){
                    pr0[cc] += w00*aa[cc] + w01*bb[cc];
                    pr1[cc] += w10*aa[cc] + w11*bb[cc];
                }
            }
            const int q = q4*2 + g;
            int m0 = 2*lp, m1 = m0 + 1;
            uint32_t off0 = (uint32_t)(m0*128 + ((q ^ permA(m0)) << 4));
            uint32_t off1 = (uint32_t)(m1*128 + ((q ^ permA(m1)) << 4));
            *(uint4*)(pA + off0) = packrow_h(pr0);
            *(uint4*)(pA + off1) = packrow_h(pr1);
        }
    };

    // ---------- pipelined main loop ----------
    stage(0);
    asm volatile("cp.async.wait_group 0;");
    __syncthreads();

    for (int c = 0; c < NCHUNK; c++){
        if (c + 1 < NCHUNK) stage(c + 1);     // overlaps with MMA(c)

        const int buf = c & 1;
        const uint32_t aA = sb + 4096 + buf*BUFSZ;
        const uint32_t aB = aA + 16384;

        #pragma unroll
        for (int ks=0; ks<4; ks++){
            uint32_t ah[2][4];
            #pragma unroll
            for (int mf=0; mf<2; mf++){
                int r  = wm*32 + mf*16 + (lane & 15);
                int kq = ks*2 + (lane >> 4);
                uint32_t off = (uint32_t)(r*128 + ((kq ^ permA(r)) << 4));
                ldsm4(ah[mf], aA + off);
            }
            int kr = ks*16 + (lane & 15);
            #pragma unroll
            for (int nb=0; nb<4; nb++){
                int nq = wn*8 + nb*2 + (lane >> 4);
                uint32_t off = (uint32_t)(kr*256 + ((nq ^ (kr & 7)) << 4));
                uint32_t bh[4];
                ldsm4t(bh, aB + off);
                #pragma unroll
                for (int mf=0; mf<2; mf++){
                    mma16816(acc[mf][nb*2],   ah[mf], bh[0], bh[1]);
                    mma16816(acc[mf][nb*2+1], ah[mf], bh[2], bh[3]);
                }
            }
        }
        asm volatile("cp.async.wait_group 0;");
        __syncthreads();
    }

    // ---- epilogue: base = EU + sum_h pat*AU, add acc, write table ----
    #pragma unroll
    for (int mf=0; mf<2; mf++){
        #pragma unroll
        for (int hh=0; hh<2; hh++){
            int row = wm*32 + mf*16 + (lane >> 2) + hh*8;
            int rlp = row >> 1, qi = row & 1;
            int rpair = p0 + rlp;
            int ra = rpair / PV, rb = rpair % PV;
            int rca = 2*ra, rcb = 2*rb + 1;
            int cq = qi ? rcb : rca;
            int gm = p0*2 + row;
            float wA[4], wB[4];
            #pragma unroll
            for (int h=0; h<NH; h++){
                wA[h] = sPat[rlp*16 + h*4 + qi*2 + 0];
                wB[h] = sPat[rlp*16 + h*4 + qi*2 + 1];
            }
            const float* eu  = g_EU + cq*PVP;
            const float* aua = g_AU + (rca*NH)*PVP;
            const float* aub = g_AU + (rcb*NH)*PVP;
            #pragma unroll
            for (int nf=0; nf<8; nf++){
                int n = wn*64 + nf*8 + (lane & 3)*2;
                float2 base = *(const float2*)(eu + n);
                #pragma unroll
                for (int h=0; h<NH; h++){
                    float2 va = *(const float2*)(aua + h*PVP + n);
                    float2 vb = *(const float2*)(aub + h*PVP + n);
                    base.x += wA[h]*va.x + wB[h]*vb.x;
                    base.y += wA[h]*va.y + wB[h]*vb.y;
                }
                if (gm < NTOK){
                    float c0 = acc[mf][nf][hh*2+0] + base.x;
                    float c1 = acc[mf][nf][hh*2+1] + base.y;
                    float* ts = g_table + (size_t)gm*PV;
                    if (n   < PV) ts[n]   = c0;
                    if (n+1 < PV) ts[n+1] = c1;
                }
            }
        }
    }
}

// ---------------- G: gather ----------------
__global__ void kG(const int* __restrict__ x, float* __restrict__ out, int B){
    int ex = blockIdx.x*8 + (threadIdx.x >> 5);
    if (ex >= B) return;
    int lane = threadIdx.x & 31;
    int a = x[ex*2], b = x[ex*2+1];
    const float2* src = (const float2*)(g_table + (size_t)(a*PV + b)*226);
    float2* dst = (float2*)(out + (size_t)ex*226);
    #pragma unroll
    for (int i=0;i<4;i++){
        int idx = lane + i*32;
        if (idx < PV) dst[idx] = src[idx];
    }
}

// ---------------- launch ----------------
extern "C" void kernel_launch(void* const* d_in, const int* in_sizes, int n_in,
                              void* d_out, int out_size){
    const int*   x   = (const int*)  d_in[0];
    const float* tok = (const float*)d_in[1];
    const float* pos = (const float*)d_in[2];
    const float* WQ  = (const float*)d_in[3];
    const float* WK  = (const float*)d_in[4];
    const float* WV  = (const float*)d_in[5];
    const float* WO  = (const float*)d_in[6];
    const float* W1  = (const float*)d_in[7];
    const float* b1  = (const float*)d_in[8];
    const float* W2  = (const float*)d_in[9];
    const float* b2  = (const float*)d_in[10];
    const float* WU  = (const float*)d_in[11];
    float* out = (float*)d_out;
    const int B = in_sizes[0] / 2;

    cudaFuncSetAttribute(kFB6, cudaFuncAttributeMaxDynamicSharedMemorySize, SMEM_TOT);

    kA1<<<569, 256>>>(WO, W1, W2, b2, WU);
    kA2<<<NCOMBO, 256>>>(tok, pos, WQ, WK, WV, W1, b1, WU);
    kFB6<<<GEMM_GRID, 256, SMEM_TOT>>>();
    kG<<<(B + 7)/8, 256>>>(x, out, B);
}